// round 14
// baseline (speedup 1.0000x reference)
#include <cuda_runtime.h>
#include <cuda_bf16.h>
#include <stdint.h>

// Problem constants (fixed by the reference setup)
#define N_BATCH 8
#define C_CH    490     // OUTPUT_DIM * GROUP * GROUP = 10*49
#define H_DIM   64
#define W_DIM   64
#define R_ROIS  2000
#define D_OUT   10
#define G_GRP   7
#define G2_CNT  49      // 7*7
#define SPATIAL_SCALE 0.0625f

#define IHP      65     // rows 0..64 of padded integral
#define P_STRIDE 67     // odd stride, conflict-free in every phase:
                        //  pass1/fixup1: lanes -> consecutive cols
                        //  pass2/fixup2: lanes -> rows, banks 67t%32=3t%32 distinct
#define PLANE_F  (IHP * P_STRIDE)   // 4355 floats = 17.42 KB

// Small scratch (L2-resident): packed bin bounds per (roi, g2), batch buckets.
__device__ uint32_t g_bounds[R_ROIS * G2_CNT];   // 392 KB
__device__ int      g_roi_sorted[R_ROIS];
__device__ int      g_batch_start[N_BATCH + 1];

// ---------------------------------------------------------------------------
// Prep (single launch): block 0 buckets ROIs by batch; other blocks compute
// packed bin bounds, concurrently.
// Bounds math: EXACT chain validated R8-R13 (bit-critical, DO NOT TOUCH):
//   bh = roi_h * fl(1/7)  (reciprocal multiply, XLA-style)
//   boundaries = SEPARATE __fmul_rn + __fadd_rn (no FMA contraction)
// ---------------------------------------------------------------------------
__global__ void __launch_bounds__(256) prep_kernel(const float* __restrict__ rois) {
    const int tid = threadIdx.x;

    if (blockIdx.x == 0) {
        __shared__ int counts[N_BATCH];
        __shared__ int cursor[N_BATCH];
        if (tid < N_BATCH) counts[tid] = 0;
        __syncthreads();
        for (int i = tid; i < R_ROIS; i += 256) {
            int b = (int)rois[i * 5];
            atomicAdd(&counts[b], 1);
        }
        __syncthreads();
        if (tid == 0) {
            int acc = 0;
            for (int n = 0; n < N_BATCH; ++n) {
                g_batch_start[n] = acc;
                cursor[n] = acc;
                acc += counts[n];
            }
            g_batch_start[N_BATCH] = acc;
        }
        __syncthreads();
        for (int i = tid; i < R_ROIS; i += 256) {
            int b = (int)rois[i * 5];
            int pos = atomicAdd(&cursor[b], 1);
            g_roi_sorted[pos] = i;
        }
        return;
    }

    const int idx = (blockIdx.x - 1) * 256 + tid;
    if (idx >= R_ROIS * G2_CNT) return;

    const int r  = idx / G2_CNT;
    const int g2 = idx - r * G2_CNT;
    const int gh = g2 / G_GRP;
    const int gw = g2 - gh * G_GRP;

    const float* roi = rois + r * 5;

    const float rsw = __fmul_rn(rintf(roi[1]), SPATIAL_SCALE);
    const float rsh = __fmul_rn(rintf(roi[2]), SPATIAL_SCALE);
    const float rew = __fmul_rn(rintf(__fadd_rn(roi[3], 1.0f)), SPATIAL_SCALE);
    const float reh = __fmul_rn(rintf(__fadd_rn(roi[4], 1.0f)), SPATIAL_SCALE);

    const float roi_w = fmaxf(__fsub_rn(rew, rsw), 0.1f);
    const float roi_h = fmaxf(__fsub_rn(reh, rsh), 0.1f);

    const float INV7 = 1.0f / 7.0f;                  // fl(1/7), compile-time rn
    const float bw = __fmul_rn(roi_w, INV7);
    const float bh = __fmul_rn(roi_h, INV7);

    const float ghf  = (float)gh,  gwf  = (float)gw;
    const float gh1f = ghf + 1.0f, gw1f = gwf + 1.0f;

    float hs_f = floorf(__fadd_rn(rsh, __fmul_rn(ghf,  bh)));
    float he_f = ceilf (__fadd_rn(rsh, __fmul_rn(gh1f, bh)));
    float ws_f = floorf(__fadd_rn(rsw, __fmul_rn(gwf,  bw)));
    float we_f = ceilf (__fadd_rn(rsw, __fmul_rn(gw1f, bw)));

    hs_f = fminf(fmaxf(hs_f, 0.f), (float)H_DIM);
    he_f = fminf(fmaxf(he_f, 0.f), (float)H_DIM);
    ws_f = fminf(fmaxf(ws_f, 0.f), (float)W_DIM);
    we_f = fminf(fmaxf(we_f, 0.f), (float)W_DIM);

    g_bounds[idx] = (uint32_t)(int)hs_f
                  | ((uint32_t)(int)he_f << 8)
                  | ((uint32_t)(int)ws_f << 16)
                  | ((uint32_t)(int)we_f << 24);
}

// ---------------------------------------------------------------------------
// Fused kernel: ONE plane per 128-thread block (R9's winning shape:
// 17.42 KB smem -> ~13 blocks/SM, stride 67 conflict-free), with both cumsum
// passes SEGMENTED 2x32 + parallel fixup so all 128 threads are active and
// the serial chain is halved. Reassociated sums are safe (R13: 1.96e-6).
// ---------------------------------------------------------------------------
__global__ void __launch_bounds__(128) fused_kernel(const float* __restrict__ feature,
                                                    float* __restrict__ out) {
    __shared__ float P[PLANE_F];

    const int plane = blockIdx.x;                 // 0 .. N*C-1
    const int n  = plane / C_CH;
    const int c  = plane - n * C_CH;
    const int g2 = c % G2_CNT;
    const int tid = threadIdx.x;

    const float* __restrict__ src = feature + (size_t)plane * (H_DIM * W_DIM);

    // Zero pads: row 0 (cols 0..64), col 0 (rows 1..64)
    if (tid < IHP) P[tid] = 0.f;
    if (tid >= 64 && tid < 128) P[(tid - 63) * P_STRIDE] = 0.f;

    // Load interior: 1024 float4 LDG, scalar STS (row base not 16B-aligned)
    {
        const float4* __restrict__ src4 = (const float4*)src;
        #pragma unroll
        for (int i = tid; i < (H_DIM * W_DIM) / 4; i += 128) {
            const float4 v = src4[i];
            const int row  = i >> 4;              // (i*4)/64
            const int col0 = (i & 15) << 2;       // (i*4)%64
            float* p = P + (row + 1) * P_STRIDE + (col0 + 1);
            p[0] = v.x; p[1] = v.y; p[2] = v.z; p[3] = v.w;
        }
    }
    __syncthreads();

    // Pass 1 (cumsum along H), segmented: col=(t&63)+1, seg rows 1..32 / 33..64
    {
        const int col = (tid & 63) + 1;
        const int r0  = 1 + (tid >> 6) * 32;
        float s = 0.f;
        #pragma unroll
        for (int k = 0; k < 32; ++k) {
            float* p = P + (r0 + k) * P_STRIDE + col;
            s += *p;
            *p = s;
        }
    }
    __syncthreads();

    // Fixup 1: rows 33..64 of each col += col total of top segment (row 32)
    {
        const int col = (tid & 63) + 1;
        const int r0  = 33 + (tid >> 6) * 16;
        const float off = P[32 * P_STRIDE + col];
        #pragma unroll
        for (int k = 0; k < 16; ++k) {
            P[(r0 + k) * P_STRIDE + col] += off;
        }
    }
    __syncthreads();

    // Pass 2 (cumsum along W), segmented: row=(t&63)+1, seg cols 1..32 / 33..64
    {
        const int row = (tid & 63) + 1;
        const int c0  = 1 + (tid >> 6) * 32;
        float* rp = P + row * P_STRIDE;
        float s = 0.f;
        #pragma unroll
        for (int k = 0; k < 32; ++k) {
            s += rp[c0 + k];
            rp[c0 + k] = s;
        }
    }
    __syncthreads();

    // Fixup 2: cols 33..64 of each row += row total of left segment (col 32)
    {
        const int row = (tid & 63) + 1;
        const int c0  = 33 + (tid >> 6) * 16;
        float* rp = P + row * P_STRIDE;
        const float off = rp[32];
        #pragma unroll
        for (int k = 0; k < 16; ++k) {
            rp[c0 + k] += off;
        }
    }
    __syncthreads();

    // Pooling: one output per ROI of batch n from this plane.
    const int s_idx = g_batch_start[n];
    const int e_idx = g_batch_start[n + 1];

    for (int i = s_idx + tid; i < e_idx; i += 128) {
        const int r = g_roi_sorted[i];
        const uint32_t pk = g_bounds[r * G2_CNT + g2];
        const int hs = (int)(pk & 0xFF);
        const int he = (int)((pk >> 8) & 0xFF);
        const int ws = (int)((pk >> 16) & 0xFF);
        const int we = (int)(pk >> 24);

        const float a00 = P[he * P_STRIDE + we];
        const float a01 = P[hs * P_STRIDE + we];
        const float a10 = P[he * P_STRIDE + ws];
        const float a11 = P[hs * P_STRIDE + ws];

        const float sum = ((a00 - a01) - a10) + a11;

        const int area = (he - hs) * (we - ws);
        const float inv_area = 1.0f / fmaxf((float)area, 1.0f);
        out[(size_t)r * C_CH + c] = (area <= 0) ? 0.f : sum * inv_area;
    }
}

extern "C" void kernel_launch(void* const* d_in, const int* in_sizes, int n_in,
                              void* d_out, int out_size) {
    const float* feature = (const float*)d_in[0];   // (8, 490, 64, 64) fp32
    const float* rois    = (const float*)d_in[1];   // (2000, 5) fp32
    float* out = (float*)d_out;                     // (2000, 10, 7, 7) fp32

    const int bounds_blocks = (R_ROIS * G2_CNT + 255) / 256;   // 383
    prep_kernel<<<1 + bounds_blocks, 256>>>(rois);
    fused_kernel<<<N_BATCH * C_CH, 128>>>(feature, out);
}